// round 12
// baseline (speedup 1.0000x reference)
#include <cuda_runtime.h>
#include <cuda_bf16.h>
#include <cstdint>

// ExponentialSmoothingLayer: s_0 = x_0; s_t = a*x_t + (1-a)*s_{t-1}, a = sigmoid(alpha[d])
// x: (B=16, T=4096, D=512) fp32 -> out same shape.
//
// v6: v5 algorithm (AGG-only truncated lookback, epoch flags, single launch)
//     retuned for residency: L=16 -> 32 KB tile -> 4 blocks/SM (100% occ target),
//     analytic truncation depth (one __logf), 4 x 8 KB TMA chunks.

#define B_  16
#define T_  4096
#define D_  512
#define L_  16
#define NTB (T_ / L_)            // 256 tiles per batch row
#define NTILES (B_ * NTB)        // 4096
#define TPB 512
#define TILE_BYTES (L_ * D_ * 4) // 32768
#define CHUNK_T 4                // timesteps per TMA chunk
#define NCHUNK (L_ / CHUNK_T)    // 4
#define CHUNK_BYTES (CHUNK_T * D_ * 4)  // 8192
#define THR      1e-10f
#define LOG_THR  -23.025851f     // ln(1e-10)

// -------- scratch (static device arrays; no runtime allocation) --------
__device__ float        g_agg [NTILES * D_];   // per-tile zero-state local last (8 MB)
__device__ float        g_incl0[B_ * D_];      // row-start true state (tile 0 only)
__device__ int          g_status[NTILES];      // ready flag: epoch+1 when published
__device__ unsigned int g_ticket;              // never reset; epoch = ticket/NTILES

// -------- PTX helpers --------
__device__ __forceinline__ int ld_acquire(const int* p) {
    int v; asm volatile("ld.acquire.gpu.s32 %0, [%1];" : "=r"(v) : "l"(p) : "memory"); return v;
}
__device__ __forceinline__ void st_release(int* p, int v) {
    asm volatile("st.release.gpu.s32 [%0], %1;" :: "l"(p), "r"(v) : "memory");
}
__device__ __forceinline__ unsigned smem_u32(const void* p) {
    unsigned a;
    asm("{ .reg .u64 t; cvta.to.shared.u64 t, %1; cvt.u32.u64 %0, t; }" : "=r"(a) : "l"(p));
    return a;
}
__device__ __forceinline__ void mbar_wait(unsigned mb) {  // parity 0, single-use
    unsigned done = 0;
    while (!done) {
        asm volatile(
            "{\n\t.reg .pred p;\n\t"
            "mbarrier.try_wait.parity.acquire.cta.shared::cta.b64 p, [%1], 0, 0x989680;\n\t"
            "selp.b32 %0, 1, 0, p;\n\t}"
            : "=r"(done) : "r"(mb) : "memory");
    }
}

__global__ void __launch_bounds__(TPB, 4)
es_scan_kernel(const float* __restrict__ x,
               const float* __restrict__ alpha,
               float* __restrict__ out) {
    extern __shared__ float tile[];                 // L_ * D_ floats (32 KB)
    __shared__ unsigned long long mbar[NCHUNK];
    __shared__ unsigned s_ticket;
    __shared__ int s_depth;

    const int tid = threadIdx.x;

    if (tid == 0) {
        const unsigned t0 = atomicAdd(&g_ticket, 1u);
        s_ticket = t0;
        s_depth  = 1;
        #pragma unroll
        for (int c = 0; c < NCHUNK; ++c)
            asm volatile("mbarrier.init.shared.b64 [%0], 1;"
                         :: "r"(smem_u32(&mbar[c])) : "memory");
        asm volatile("fence.proxy.async.shared::cta;" ::: "memory");

        // issue the chunk loads immediately (before block-wide sync)
        const unsigned id0 = t0 & (NTILES - 1);
        const int b0 = (int)(id0 & (B_ - 1)), tb0 = (int)(id0 >> 4);
        const size_t base0 = ((size_t)b0 * T_ + (size_t)tb0 * L_) * (size_t)D_;
        #pragma unroll
        for (int c = 0; c < NCHUNK; ++c) {
            unsigned mb = smem_u32(&mbar[c]);
            asm volatile("mbarrier.arrive.expect_tx.shared.b64 _, [%0], %1;"
                         :: "r"(mb), "r"((unsigned)CHUNK_BYTES) : "memory");
            asm volatile("cp.async.bulk.shared::cta.global.mbarrier::complete_tx::bytes "
                         "[%0], [%1], %2, [%3];"
                         :: "r"(smem_u32(tile + (size_t)c * (CHUNK_T * D_))),
                            "l"(x + base0 + (size_t)c * (CHUNK_T * D_)),
                            "r"((unsigned)CHUNK_BYTES), "r"(mb) : "memory");
        }
    }
    __syncthreads();

    const unsigned tk    = s_ticket;
    const unsigned epoch = tk >> 12;                // tk / NTILES
    const unsigned id    = tk & (NTILES - 1);
    const int b   = (int)(id & (B_ - 1));           // round-robin rows
    const int tb  = (int)(id >> 4);
    const int lin = b * NTB + tb;
    const int ready = (int)(epoch + 1u);
    const size_t base = ((size_t)b * T_ + (size_t)tb * L_) * (size_t)D_;

    // per-channel coefficients (overlaps TMA)
    const float av = alpha[tid];
    const float a  = 1.0f / (1.0f + __expf(-av));
    const float q  = 1.0f - a;
    float Q = q;                                    // Q = q^16
    #pragma unroll
    for (int i = 0; i < 4; ++i) Q *= Q;

    // analytic truncation depth: #terms with Q^i >= THR  (block max)
    {
        // depth = 1 + floor(ln(THR)/ln(Q)); Q in (0,1) -> logQ < 0
        float lq = __logf(Q);
        int nd = 1 + (int)(LOG_THR / lq);           // Q->0: ratio->0 -> nd=1
        nd = max(1, min(nd, 96));
        #pragma unroll
        for (int off = 16; off > 0; off >>= 1)
            nd = max(nd, __shfl_xor_sync(0xffffffffu, nd, off));
        if ((tid & 31) == 0) atomicMax(&s_depth, nd);
    }

    // ---- chunked scan: wait chunk, scan its timesteps ----
    float s = 0.0f, x0 = 0.0f;
    #pragma unroll
    for (int c = 0; c < NCHUNK; ++c) {
        mbar_wait(smem_u32(&mbar[c]));
        #pragma unroll
        for (int t = c * CHUNK_T; t < (c + 1) * CHUNK_T; ++t) {
            float v = tile[t * D_ + tid];
            if (t == 0) x0 = v;
            s = fmaf(q, s, a * v);
            tile[t * D_ + tid] = s;
        }
    }
    const float last = s;

    // ---- publish (AGG for tb>0; exact row-start state for tb==0) ----
    if (tb == 0) g_incl0[b * D_ + tid] = fmaf(Q, x0, last);
    else         g_agg[(size_t)lin * D_ + tid] = last;
    __threadfence();
    __syncthreads();                                // also publishes s_depth
    if (tid == 0) st_release(&g_status[lin], ready);

    // ---- truncated AGG-only lookback ----
    float carry;
    if (tb == 0) {
        carry = x0;                                 // s_0 = x_0  <=>  S_in = x_0
    } else {
        const int dep = min(s_depth, tb);           // block-uniform
        carry = 0.0f;
        float coef = 1.0f;
        int done = 0;
        while (done < dep) {                        // 1-2 segments typical
            const int seg = min(32, dep - done);
            if (tid < 32) {                         // warp 0: wait seg ready flags
                const int i = done + tid;
                const int j = tb - 1 - i;
                const int* sp = &g_status[b * NTB + (j < 0 ? 0 : j)];
                for (;;) {
                    int st = (tid < seg) ? ld_acquire(sp) : ready;
                    if (__all_sync(0xffffffffu, st >= ready)) break;
                    __nanosleep(40);
                }
            }
            __syncthreads();
            #pragma unroll 1
            for (int ii = 0; ii < seg; ++ii) {
                const int j = tb - 1 - (done + ii);
                if (coef >= THR) {
                    const float val = (j == 0) ? g_incl0[b * D_ + tid]
                                               : g_agg[(size_t)(b * NTB + j) * D_ + tid];
                    carry = fmaf(coef, val, carry);
                }
                coef *= Q;
            }
            done += seg;
        }
    }

    // ---- fixup + coalesced store: s_{t0+t} = local_t + q^{t+1} * S_in ----
    float* op = out + base + tid;
    float c = q;
    #pragma unroll
    for (int t = 0; t < L_; ++t) {
        op[(size_t)t * D_] = fmaf(c, carry, tile[t * D_ + tid]);
        c *= q;
    }
}

extern "C" void kernel_launch(void* const* d_in, const int* in_sizes, int n_in,
                              void* d_out, int out_size) {
    const float* x     = (const float*)d_in[0];   // (16, 4096, 512) fp32
    const float* alpha = (const float*)d_in[1];   // (1, 1, 512) fp32
    float* out = (float*)d_out;
    (void)in_sizes; (void)n_in; (void)out_size;

    static bool attr_set = false;
    if (!attr_set) {
        cudaFuncSetAttribute(es_scan_kernel,
                             cudaFuncAttributeMaxDynamicSharedMemorySize,
                             TILE_BYTES);
        attr_set = true;
    }

    es_scan_kernel<<<NTILES, TPB, TILE_BYTES>>>(x, alpha, out);
}